// round 8
// baseline (speedup 1.0000x reference)
#include <cuda_runtime.h>
#include <cstdint>

// 9-DoF alignment, one WARP per batch. cp.async (LDGSTS) staging:
// in-flight bytes live in the memory pipeline + smem instead of registers,
// breaking the regfile-imposed MLP cap seen in R5-R7.
//
// Per warp: 8 chunks of 128 points. 3-slot smem ring (3072B/slot: x then y),
// issue chunk c+2 while consuming chunk c (up to 6KB in flight per warp).
// Readback: 3 scalar LDS.32 per point, bank-conflict-free (bank = 3*lane+d).
// No __syncthreads anywhere; only cp.async.wait_group + __syncwarp.

#define SLOT_BYTES   3072   // 1536B x + 1536B y (128 points * 12B each)
#define WARP_SMEM    (3 * SLOT_BYTES)          // 9216B ring per warp
#define CTA_SMEM     (8 * WARP_SMEM)           // 73728B per CTA (8 warps)

__device__ __forceinline__ void cp_async16(uint32_t saddr, const void* gaddr) {
    asm volatile("cp.async.cg.shared.global [%0], [%1], 16;\n"
                 :: "r"(saddr), "l"(gaddr));
}
__device__ __forceinline__ void cp_commit() {
    asm volatile("cp.async.commit_group;\n");
}
template <int N>
__device__ __forceinline__ void cp_wait() {
    asm volatile("cp.async.wait_group %0;\n" :: "n"(N));
}

__global__ __launch_bounds__(256, 3)
void align9dof_kernel(const float* __restrict__ x,
                      const float* __restrict__ mu_x,
                      const float* __restrict__ y,
                      const float* __restrict__ mu_y,
                      float* __restrict__ out,
                      int B)
{
    extern __shared__ char smem_dyn[];

    const int warp = threadIdx.x >> 5;
    const int lane = threadIdx.x & 31;
    const int b    = blockIdx.x * 8 + warp;
    if (b >= B) return;

    // Per-batch means (uniform broadcast loads)
    const float mx0 = mu_x[b * 3 + 0];
    const float mx1 = mu_x[b * 3 + 1];
    const float mx2 = mu_x[b * 3 + 2];
    const float my0 = mu_y[b * 3 + 0];
    const float my1 = mu_y[b * 3 + 1];
    const float my2 = mu_y[b * 3 + 2];

    const char* __restrict__ gx = (const char*)(x + (size_t)b * 3072);
    const char* __restrict__ gy = (const char*)(y + (size_t)b * 3072);

    char* wbase = smem_dyn + warp * WARP_SMEM;
    const uint32_t sbase = (uint32_t)__cvta_generic_to_shared(wbase);

    // Issue one 128-point chunk: 3 x 512B per array via 16B cp.async per lane
    auto issue_chunk = [&](int c) {
        const uint32_t s = sbase + (c % 3) * SLOT_BYTES + lane * 16;
        const int      g = c * 1536 + lane * 16;
#pragma unroll
        for (int k = 0; k < 3; k++) {
            cp_async16(s + k * 512,        gx + g + k * 512);
            cp_async16(s + 1536 + k * 512, gy + g + k * 512);
        }
        cp_commit();
    };

    // Prologue: chunks 0 and 1 in flight
    issue_chunk(0);
    issue_chunk(1);

    float v[11];  // c00..c22, sxx, syy
#pragma unroll
    for (int i = 0; i < 11; i++) v[i] = 0.0f;

#pragma unroll
    for (int c = 0; c < 8; c++) {
        if (c < 6) issue_chunk(c + 2);

        // Wait until chunk c's group has completed
        if (c < 6)      cp_wait<2>();
        else if (c == 6) cp_wait<1>();
        else             cp_wait<0>();
        __syncwarp();

        const float* fx = (const float*)(wbase + (c % 3) * SLOT_BYTES);
        const float* fy = fx + 384;  // +1536B

#pragma unroll
        for (int q = 0; q < 4; q++) {
            const int p = q * 32 + lane;
            const float u0 = fx[3 * p + 0] - mx0;
            const float u1 = fx[3 * p + 1] - mx1;
            const float u2 = fx[3 * p + 2] - mx2;
            const float w0 = fy[3 * p + 0] - my0;
            const float w1 = fy[3 * p + 1] - my1;
            const float w2 = fy[3 * p + 2] - my2;
            v[0] = fmaf(u0, w0, v[0]); v[1] = fmaf(u0, w1, v[1]); v[2] = fmaf(u0, w2, v[2]);
            v[3] = fmaf(u1, w0, v[3]); v[4] = fmaf(u1, w1, v[4]); v[5] = fmaf(u1, w2, v[5]);
            v[6] = fmaf(u2, w0, v[6]); v[7] = fmaf(u2, w1, v[7]); v[8] = fmaf(u2, w2, v[8]);
            v[9]  = fmaf(u0, u0, fmaf(u1, u1, fmaf(u2, u2, v[9])));
            v[10] = fmaf(w0, w0, fmaf(w1, w1, fmaf(w2, w2, v[10])));
        }
        __syncwarp();  // all lanes done reading slot before it is refilled
    }

    // Warp butterfly reduction: all lanes end with the full batch sums
#pragma unroll
    for (int off = 16; off > 0; off >>= 1) {
#pragma unroll
        for (int i = 0; i < 11; i++)
            v[i] += __shfl_xor_sync(0xFFFFFFFFu, v[i], off);
    }

    // ---- Polar factor via determinant-scaled Newton (all lanes, redundant) ----
    float fro2 = 0.0f;
#pragma unroll
    for (int i = 0; i < 9; i++) fro2 = fmaf(v[i], v[i], fro2);
    const float invf = rsqrtf(fmaxf(fro2, 1e-30f));

    float X[9];
#pragma unroll
    for (int i = 0; i < 9; i++) X[i] = v[i] * invf;

#pragma unroll
    for (int it = 0; it < 8; it++) {
        float C[9];  // cofactor matrix: X^{-T} = C / det
        C[0] = X[4] * X[8] - X[5] * X[7];
        C[1] = X[5] * X[6] - X[3] * X[8];
        C[2] = X[3] * X[7] - X[4] * X[6];
        C[3] = X[2] * X[7] - X[1] * X[8];
        C[4] = X[0] * X[8] - X[2] * X[6];
        C[5] = X[1] * X[6] - X[0] * X[7];
        C[6] = X[1] * X[5] - X[2] * X[4];
        C[7] = X[2] * X[3] - X[0] * X[5];
        C[8] = X[0] * X[4] - X[1] * X[3];
        float det = X[0] * C[0] + X[1] * C[1] + X[2] * C[2];
        float ad  = fmaxf(fabsf(det), 1e-30f);
        float eta = rcbrtf(ad);            // |det|^{-1/3}
        float k1  = 0.5f * eta;
        float k2  = 0.5f / (eta * det);    // keeps det's sign
#pragma unroll
        for (int i = 0; i < 9; i++) X[i] = k1 * X[i] + k2 * C[i];
    }

    // t = mu_y - R mu_x
    const float t0 = my0 - (X[0] * mx0 + X[1] * mx1 + X[2] * mx2);
    const float t1 = my1 - (X[3] * mx0 + X[4] * mx1 + X[5] * mx2);
    const float t2 = my2 - (X[6] * mx0 + X[7] * mx1 + X[8] * mx2);

    const float sf = sqrtf(v[10]) / (sqrtf(v[9]) + 1e-6f);

    // ---- Coalesced predicated stores ----
    if (lane < 9) {
        float r = (lane == 0) ? X[0] :
                  (lane == 1) ? X[1] :
                  (lane == 2) ? X[2] :
                  (lane == 3) ? X[3] :
                  (lane == 4) ? X[4] :
                  (lane == 5) ? X[5] :
                  (lane == 6) ? X[6] :
                  (lane == 7) ? X[7] : X[8];
        out[(size_t)b * 9 + lane] = r;
    }
    if (lane < 3) {
        float tv = (lane == 0) ? t0 : (lane == 1) ? t1 : t2;
        out[(size_t)B * 9 + (size_t)b * 3 + lane] = tv;
    }
    if (lane == 0) {
        out[(size_t)B * 12 + b] = sf;
    }
}

extern "C" void kernel_launch(void* const* d_in, const int* in_sizes, int n_in,
                              void* d_out, int out_size)
{
    const float* x    = (const float*)d_in[0];
    const float* mu_x = (const float*)d_in[1];
    const float* y    = (const float*)d_in[2];
    const float* mu_y = (const float*)d_in[3];
    float* out        = (float*)d_out;

    const int B = in_sizes[1] / 3;  // mu_x is [B,3]

    cudaFuncSetAttribute(align9dof_kernel,
                         cudaFuncAttributeMaxDynamicSharedMemorySize, CTA_SMEM);

    align9dof_kernel<<<(B + 7) / 8, 256, CTA_SMEM>>>(x, mu_x, y, mu_y, out, B);
}